// round 11
// baseline (speedup 1.0000x reference)
#include <cuda_runtime.h>

#define FULL 0xffffffffu
typedef unsigned long long ull;

constexpr int   RAYS_TOTAL = 16384;
constexpr float NEARF = 2.0f, FARF = 6.0f;
constexpr int   RPB = 4;   // rays (warps) per block, 128-thread blocks

__device__ __forceinline__ ull pack2(float lo, float hi) {
    ull r; asm("mov.b64 %0,{%1,%2};" : "=l"(r) : "f"(lo), "f"(hi)); return r;
}
__device__ __forceinline__ void unpack2(ull v, float& lo, float& hi) {
    asm("mov.b64 {%0,%1},%2;" : "=f"(lo), "=f"(hi) : "l"(v));
}
__device__ __forceinline__ ull fma2(ull a, ull b, ull c) {
    ull d; asm("fma.rn.f32x2 %0,%1,%2,%3;" : "=l"(d) : "l"(a), "l"(b), "l"(c)); return d;
}
__device__ __forceinline__ ull mul2(ull a, ull b) {
    ull d; asm("mul.rn.f32x2 %0,%1,%2;" : "=l"(d) : "l"(a), "l"(b)); return d;
}
__device__ __forceinline__ ull relu2(ull v) {
    float lo, hi; unpack2(v, lo, hi);
    return pack2(fmaxf(lo, 0.f), fmaxf(hi, 0.f));
}
__device__ __forceinline__ float sigm(float x) {
    return __fdividef(1.f, 1.f + __expf(-x));
}

// ---- weights in constant: ONLY the transposed layer-2 + b2 need repacking.
// cAll[0..63]  (ulonglong2) : w2t entry 4q+c: .x = {W2[4q][c],W2[4q+1][c]}, .y = {W2[4q+2][c],W2[4q+3][c]}
// cAll[64]                  : b2 = {(b2_0,b2_1),(b2_2,b2_3)}
// W1/b1 are consumed RAW from the input pointers (their natural layout IS the pair packing).
__constant__ ulonglong2 cAll[65];
__device__   ulonglong2 g_stage[65];

__global__ void pack_weights(const float* __restrict__ W2, const float* __restrict__ b2f)
{
    const int t = threadIdx.x;   // 0..63
    ull* w2t = (ull*)g_stage;
    int e = t;
    #pragma unroll
    for (int k = 0; k < 2; ++k, e += 64) {
        const int ent = e >> 1, half = e & 1;   // ent = 4q+c
        const int q = ent >> 2, c = ent & 3;
        const int u0 = 4 * q + 2 * half;
        w2t[e] = pack2(W2[u0 * 4 + c], W2[(u0 + 1) * 4 + c]);
    }
    if (t == 0) {
        float* s = (float*)g_stage;
        s[256] = b2f[0]; s[257] = b2f[1]; s[258] = b2f[2]; s[259] = b2f[3];
    }
}

// Branchless 7-step counts over sorted a[0..63].
__device__ __forceinline__ int count_lt64(const float* __restrict__ a, float x) {
    int p = 0;
    p += (a[p + 31] < x) ? 32 : 0;
    p += (a[p + 15] < x) ? 16 : 0;
    p += (a[p + 7]  < x) ? 8  : 0;
    p += (a[p + 3]  < x) ? 4  : 0;
    p += (a[p + 1]  < x) ? 2  : 0;
    p += (a[p]      < x) ? 1  : 0;
    p += (a[p]      < x) ? 1  : 0;
    return p;
}
__device__ __forceinline__ int count_le64(const float* __restrict__ a, float x) {
    int p = 0;
    p += (a[p + 31] <= x) ? 32 : 0;
    p += (a[p + 15] <= x) ? 16 : 0;
    p += (a[p + 7]  <= x) ? 8  : 0;
    p += (a[p + 3]  <= x) ? 4  : 0;
    p += (a[p + 1]  <= x) ? 2  : 0;
    p += (a[p]      <= x) ? 1  : 0;
    p += (a[p]      <= x) ? 1  : 0;
    return p;
}

// Tiny MLP at TWO points of one ray, layer-1 folded: h = relu(P + z*Q).
// pq (shared, ulonglong2[32]): [j] = (P_pair_j, Q_pair_j), pair j = units {2j,2j+1}.
// Layer-2 weights + b2 from __constant__ (LDC warp-broadcast).
// Outputs (sigma, r, g, b) as float4 — directly storable payload.
__device__ __forceinline__ void field_eval2(
    float z0, float z1,
    const ulonglong2* __restrict__ pq,
    float4& o0, float4& o1)
{
    const ulonglong2* __restrict__ w2t = cAll;
    float b20, b21, b22, b23;
    unpack2(cAll[64].x, b20, b21);
    unpack2(cAll[64].y, b22, b23);
    const ull Z0 = pack2(z0, z0), Z1 = pack2(z1, z1);
    ull a00 = pack2(b20, 0.f), a01 = pack2(b21, 0.f);
    ull a02 = pack2(b22, 0.f), a03 = pack2(b23, 0.f);
    ull a10 = a00, a11 = a01, a12 = a02, a13 = a03;
    #pragma unroll
    for (int q = 0; q < 16; ++q) {
        const ulonglong2 p0 = pq[2 * q], p1 = pq[2 * q + 1];
        const ull h0a = relu2(fma2(Z0, p0.y, p0.x));
        const ull h0b = relu2(fma2(Z0, p1.y, p1.x));
        const ull h1a = relu2(fma2(Z1, p0.y, p0.x));
        const ull h1b = relu2(fma2(Z1, p1.y, p1.x));
        const ulonglong2 T0 = w2t[4 * q + 0], T1 = w2t[4 * q + 1];
        const ulonglong2 T2 = w2t[4 * q + 2], T3 = w2t[4 * q + 3];
        a00 = fma2(h0a, T0.x, a00); a00 = fma2(h0b, T0.y, a00);
        a01 = fma2(h0a, T1.x, a01); a01 = fma2(h0b, T1.y, a01);
        a02 = fma2(h0a, T2.x, a02); a02 = fma2(h0b, T2.y, a02);
        a03 = fma2(h0a, T3.x, a03); a03 = fma2(h0b, T3.y, a03);
        a10 = fma2(h1a, T0.x, a10); a10 = fma2(h1b, T0.y, a10);
        a11 = fma2(h1a, T1.x, a11); a11 = fma2(h1b, T1.y, a11);
        a12 = fma2(h1a, T2.x, a12); a12 = fma2(h1b, T2.y, a12);
        a13 = fma2(h1a, T3.x, a13); a13 = fma2(h1b, T3.y, a13);
    }
    float lo, hi;
    unpack2(a00, lo, hi); o0.x = lo + hi;
    unpack2(a01, lo, hi); o0.y = sigm(lo + hi);
    unpack2(a02, lo, hi); o0.z = sigm(lo + hi);
    unpack2(a03, lo, hi); o0.w = sigm(lo + hi);
    unpack2(a10, lo, hi); o1.x = lo + hi;
    unpack2(a11, lo, hi); o1.y = sigm(lo + hi);
    unpack2(a12, lo, hi); o1.z = sigm(lo + hi);
    unpack2(a13, lo, hi); o1.w = sigm(lo + hi);
}

__global__ void __launch_bounds__(RPB * 32, 11)
nerf_kernel(const float* __restrict__ ro,   const float* __restrict__ rdi,
            const float* __restrict__ tform, const float* __restrict__ noise,
            const float* __restrict__ usmp,
            const float* __restrict__ gW1, const float* __restrict__ gb1,
            float* __restrict__ orgb, float* __restrict__ odep, float* __restrict__ omsk)
{
    // Per-warp shared (3 KB): z (512B) + cdf/fine-z (512B) + payload (2 KB)
    __shared__ float  sZ [RPB][128];   // coarse z [0..63]; sorted all-z after scatter
    __shared__ float  sSg[RPB][128];   // cdf [0..62] + pad [63]; sorted fine z [64..127]
    __shared__ float4 sScat[RPB][128]; // pre-scatter: o-stash [0..63], u-stash [64..95], PQ [96..127]
                                       // post-scatter: (sigma, r, g, b) per sorted sample

    const int tid = threadIdx.x;
    const int wrp = tid >> 5, lane = tid & 31;
    const int ray = blockIdx.x * RPB + wrp;
    float*  zw   = sZ[wrp];
    float*  sgw  = sSg[wrp];
    float*  sf   = sgw + 64;                 // sorted fine z
    float4* scat = sScat[wrp];

    const float ox = ro[ray * 3 + 0], oy = ro[ray * 3 + 1], oz = ro[ray * 3 + 2];
    float dx = rdi[ray * 3 + 0], dy = rdi[ray * 3 + 1], dz = rdi[ray * 3 + 2];
    {
        const float rinvn = rsqrtf(dx * dx + dy * dy + dz * dz);
        dx *= rinvn; dy *= rinvn; dz *= rinvn;
    }

    // ---- u prefetch -> stash in shared (keeps LDG latency hidden, frees regs) ----
    {
        const float uu0 = usmp[ray * 64 + lane];
        const float uu1 = usmp[ray * 64 + lane + 32];
        *(float2*)&scat[64 + lane] = make_float2(uu0, uu1);
    }

    // ---- PQ precompute: W1/b1 read RAW from inputs (natural layout == pair packing) ----
    {
        const ull W1x = ((const ull*)gW1)[lane];
        const ull W1y = ((const ull*)(gW1 + 64))[lane];
        const ull W1z = ((const ull*)(gW1 + 128))[lane];
        const ull B1  = ((const ull*)gb1)[lane];
        const ull P = fma2(pack2(ox, ox), W1x, fma2(pack2(oy, oy), W1y, fma2(pack2(oz, oz), W1z, B1)));
        const ull Q = fma2(pack2(dx, dx), W1x, fma2(pack2(dy, dy), W1y, mul2(pack2(dz, dz), W1z)));
        ((ulonglong2*)&scat[96])[lane] = make_ulonglong2(P, Q);
    }
    const ulonglong2* __restrict__ pq = (const ulonglong2*)&scat[96];

    // ---- coarse stratified z (sorted by construction) ----
    const float2 nzp = ((const float2*)(noise + ray * 64))[lane];
    const int i0 = 2 * lane, i1 = i0 + 1;
    const float z0 = NEARF + (FARF - NEARF) * (((float)i0 + nzp.x) * (1.f / 64.f));
    const float z1 = NEARF + (FARF - NEARF) * (((float)i1 + nzp.y) * (1.f / 64.f));
    zw[i0] = z0; zw[i1] = z1;
    // intra-phase neighbor traffic below goes through shfl; zw reads gated by later syncwarp

    // ---- coarse MLP; stash outputs to shared so they don't occupy regs ----
    float s1 = 0.f, s2 = 0.f;   // pooled pdf terms, built via shfl
    {
        float4 o0, o1;
        field_eval2(z0, z1, pq, o0, o1);
        scat[2 * lane]     = o0;
        scat[2 * lane + 1] = o1;

        // ---- coarse compositing weights (warp multiplicative scan; neighbors via shfl) ----
        const float d0 = z1 - z0;
        const float znx = __shfl_down_sync(FULL, z0, 1);   // zw[i1+1] == next lane's z0
        const float d1 = (lane == 31) ? 1e10f : (znx - z1);
        const float e0 = __expf(-fmaxf(o0.x, 0.f) * d0);
        const float e1 = __expf(-fmaxf(o1.x, 0.f) * d1);
        const float a0 = 1.f - e0, a1 = 1.f - e1;
        const float m0 = 1.f - a0 + 1e-10f, m1 = 1.f - a1 + 1e-10f;
        float v = m0 * m1;
        #pragma unroll
        for (int off = 1; off < 32; off <<= 1) {
            float t = __shfl_up_sync(FULL, v, off);
            if (lane >= off) v *= t;
        }
        float ex = __shfl_up_sync(FULL, v, 1);
        if (lane == 0) ex = 1.f;
        const float w0 = a0 * ex;          // weight at i0
        const float w1 = a1 * ex * m0;     // weight at i1
        const float w0n = __shfl_down_sync(FULL, w0, 1);
        const float w1n = __shfl_down_sync(FULL, w1, 1);
        if (lane < 31) {
            const float mA = fmaxf(w0, w1), mB = fmaxf(w1, w0n), mC = fmaxf(w0n, w1n);
            s1 = 0.5f * (mA + mB) + 0.01f;
            s2 = 0.5f * (mB + mC) + 0.01f;
        }
    }

    // ---- pdf -> cdf (63 entries in sgw[0..62]; sgw[63] = +pad) ----
    {
        const float pr = s1 + s2;
        float v = pr;
        #pragma unroll
        for (int off = 1; off < 32; off <<= 1) {
            float t = __shfl_up_sync(FULL, v, off);
            if (lane >= off) v += t;
        }
        const float tot = __shfl_sync(FULL, v, 30);
        const float rv = __fdividef(1.f, tot);
        const float ex = v - pr;
        if (lane == 0) { sgw[0] = 0.f; sgw[63] = 2.f; }
        if (lane < 31) {
            sgw[2 * lane + 1] = (ex + s1) * rv;
            sgw[2 * lane + 2] = v * rv;
        }
    }
    __syncwarp();   // orders zw/sgw/u-stash writes before the searches below

    // ---- inverse-CDF fine samples (2 per lane, unsorted) ----
    float zs0 = 0.f, zs1 = 0.f;
    {
        const float2 upair = *(const float2*)&scat[64 + lane];
        #pragma unroll
        for (int k = 0; k < 2; ++k) {
            const float u = (k == 0) ? upair.x : upair.y;
            const int lo = count_le64(sgw, u);         // in [1,63] (cdf[0]=0 <= u, pad=2 > u)
            const int below = lo - 1;
            const int above = lo < 62 ? lo : 62;
            const float cbv = sgw[below], cav = sgw[above];
            float den = cav - cbv;
            if (den < 1e-5f) den = 1.f;
            const float t  = __fdividef(u - cbv, den);
            const float bb = 0.5f * (zw[below] + zw[below + 1]);
            const float ba = 0.5f * (zw[above] + zw[above + 1]);
            const float zz = fmaf(t, ba - bb, bb);
            if (k == 0) zs0 = zz; else zs1 = zz;
        }
    }

    // ---- bitonic sort of the 64 fine samples (registers + shfl) ----
    float v0 = zs0, v1 = zs1;
    {
        const int e0l = lane, e1l = lane + 32;
        #pragma unroll
        for (int k = 2; k <= 64; k <<= 1) {
            #pragma unroll
            for (int j = k >> 1; j >= 1; j >>= 1) {
                if (j == 32) {
                    const float lo = fminf(v0, v1), hi = fmaxf(v0, v1);
                    v0 = lo; v1 = hi;
                } else {
                    const float t0 = __shfl_xor_sync(FULL, v0, j);
                    const bool keep0 = (((e0l & k) == 0) == ((e0l & j) == 0));
                    v0 = keep0 ? fminf(v0, t0) : fmaxf(v0, t0);
                    const float t1 = __shfl_xor_sync(FULL, v1, j);
                    const bool keep1 = (((e1l & k) == 0) == ((e1l & j) == 0));
                    v1 = keep1 ? fminf(v1, t1) : fmaxf(v1, t1);
                }
            }
        }
    }
    __syncwarp();                                  // cdf/u reads done before sf write
    sf[lane] = v0;
    sf[lane + 32] = v1;

    // ---- fine MLP at SORTED fine positions ----
    float4 f0, f1;
    field_eval2(v0, v1, pq, f0, f1);
    __syncwarp();                                  // sf fully written

    // ---- merge ranks: coarse sorted x fine sorted (branchless searches) ----
    const float zr0 = zw[i0], zr1 = zw[i1];
    const int r0 = i0 + count_lt64(sf, zr0);       // ties: coarse first
    const int r1 = i1 + count_lt64(sf, zr1);
    const int r2 = lane      + count_le64(zw, v0); // ties: fine after coarse
    const int r3 = lane + 32 + count_le64(zw, v1);
    const float4 o0 = scat[2 * lane];              // restore coarse outputs
    const float4 o1 = scat[2 * lane + 1];
    __syncwarp();                                  // all reads (incl. PQ, o-stash) done before scatter

    zw[r0] = zr0; scat[r0] = o0;
    zw[r1] = zr1; scat[r1] = o1;
    zw[r2] = v0;  scat[r2] = f0;
    zw[r3] = v1;  scat[r3] = f1;
    __syncwarp();

    // ---- final compositing over 128 sorted samples (4 per lane, vectorized loads) ----
    const int p = 4 * lane;
    const float4 zq = *(const float4*)(zw + p);
    const float  zn = (lane < 31) ? zw[p + 4] : 0.f;
    const float4 eA = scat[p], eB = scat[p + 1], eC = scat[p + 2], eD = scat[p + 3];

    const float dda = zq.y - zq.x, ddb = zq.z - zq.y, ddc = zq.w - zq.z;
    const float ddd = (lane == 31) ? 1e10f : (zn - zq.w);
    const float ea = __expf(-fmaxf(eA.x, 0.f) * dda);
    const float eb = __expf(-fmaxf(eB.x, 0.f) * ddb);
    const float ec = __expf(-fmaxf(eC.x, 0.f) * ddc);
    const float ed = __expf(-fmaxf(eD.x, 0.f) * ddd);
    const float aa = 1.f - ea, ab = 1.f - eb, ac = 1.f - ec, ad = 1.f - ed;
    const float ma = 1.f - aa + 1e-10f, mb = 1.f - ab + 1e-10f;
    const float mc = 1.f - ac + 1e-10f, md = 1.f - ad + 1e-10f;
    const float q0 = ma, q1 = ma * mb, q2 = q1 * mc, q3 = q2 * md;
    float v = q3;
    #pragma unroll
    for (int off = 1; off < 32; off <<= 1) {
        float t = __shfl_up_sync(FULL, v, off);
        if (lane >= off) v *= t;
    }
    float E = __shfl_up_sync(FULL, v, 1);
    if (lane == 0) E = 1.f;
    const float wA = aa * E, wB = ab * E * q0, wC = ac * E * q1, wD = ad * E * q2;

    float SW = wA + wB + wC + wD;
    float SZ = wA * zq.x + wB * zq.y + wC * zq.z + wD * zq.w;
    float SR = wA * eA.y + wB * eB.y + wC * eC.y + wD * eD.y;
    float SG = wA * eA.z + wB * eB.z + wC * eC.z + wD * eD.z;
    float SB = wA * eA.w + wB * eB.w + wC * eC.w + wD * eD.w;

    #pragma unroll
    for (int off = 16; off; off >>= 1) {
        SW += __shfl_xor_sync(FULL, SW, off);
        SZ += __shfl_xor_sync(FULL, SZ, off);
        SR += __shfl_xor_sync(FULL, SR, off);
        SG += __shfl_xor_sync(FULL, SG, off);
        SB += __shfl_xor_sync(FULL, SB, off);
    }

    if (lane == 0) {
        orgb[ray * 3 + 0] = SR;
        orgb[ray * 3 + 1] = SG;
        orgb[ray * 3 + 2] = SB;
        // reload + renormalize direction (cheaper than 3 regs live for the whole kernel)
        float ddx = rdi[ray * 3 + 0], ddy = rdi[ray * 3 + 1], ddz = rdi[ray * 3 + 2];
        const float rn = rsqrtf(ddx * ddx + ddy * ddy + ddz * ddz);
        const float* Tm = tform + (ray >> 12) * 16;
        const float vz = rn * (ddx * Tm[2] + ddy * Tm[6] + ddz * Tm[10]);
        odep[ray] = -vz * SZ;
        omsk[ray] = SW;
    }
}

extern "C" void kernel_launch(void* const* d_in, const int* in_sizes, int n_in,
                              void* d_out, int out_size)
{
    const float* ro    = (const float*)d_in[0];
    const float* rdi   = (const float*)d_in[1];
    const float* tform = (const float*)d_in[2];
    const float* noise = (const float*)d_in[3];
    const float* usmp  = (const float*)d_in[4];
    const float* W1    = (const float*)d_in[5];
    const float* b1    = (const float*)d_in[6];
    const float* W2    = (const float*)d_in[7];
    const float* b2    = (const float*)d_in[8];

    float* out = (float*)d_out;
    float* orgb = out;
    float* odep = out + RAYS_TOTAL * 3;
    float* omsk = odep + RAYS_TOTAL;

    pack_weights<<<1, 64>>>(W2, b2);
    void* stage_addr = nullptr;
    cudaGetSymbolAddress(&stage_addr, g_stage);
    cudaMemcpyToSymbolAsync(cAll, stage_addr, sizeof(g_stage), 0,
                            cudaMemcpyDeviceToDevice, 0);

    dim3 grid(RAYS_TOTAL / RPB);   // 4096 blocks, 1 ray per warp, 4 warps/block
    dim3 block(RPB * 32);
    nerf_kernel<<<grid, block>>>(ro, rdi, tform, noise, usmp, W1, b1,
                                 orgb, odep, omsk);
}

// round 13
// speedup vs baseline: 1.0059x; 1.0059x over previous
#include <cuda_runtime.h>

#define FULL 0xffffffffu
typedef unsigned long long ull;

constexpr int   RAYS_TOTAL = 16384;
constexpr float NEARF = 2.0f, FARF = 6.0f;
constexpr int   RPB = 4;   // rays (warps) per block, 128-thread blocks

__device__ __forceinline__ ull pack2(float lo, float hi) {
    ull r; asm("mov.b64 %0,{%1,%2};" : "=l"(r) : "f"(lo), "f"(hi)); return r;
}
__device__ __forceinline__ void unpack2(ull v, float& lo, float& hi) {
    asm("mov.b64 {%0,%1},%2;" : "=f"(lo), "=f"(hi) : "l"(v));
}
__device__ __forceinline__ ull fma2(ull a, ull b, ull c) {
    ull d; asm("fma.rn.f32x2 %0,%1,%2,%3;" : "=l"(d) : "l"(a), "l"(b), "l"(c)); return d;
}
__device__ __forceinline__ ull mul2(ull a, ull b) {
    ull d; asm("mul.rn.f32x2 %0,%1,%2;" : "=l"(d) : "l"(a), "l"(b)); return d;
}
// ReLU on both packed halves (2x FMNMX — max.f32x2 does NOT exist on this toolchain).
__device__ __forceinline__ ull relu2(ull v) {
    float lo, hi; unpack2(v, lo, hi);
    return pack2(fmaxf(lo, 0.f), fmaxf(hi, 0.f));
}
__device__ __forceinline__ float sigm(float x) {
    return __fdividef(1.f, 1.f + __expf(-x));
}

// ---- weights in constant: ONLY the transposed layer-2 + b2 need repacking.
// cAll[0..63]  (ulonglong2) : w2t entry 4q+c: .x = {W2[4q][c],W2[4q+1][c]}, .y = {W2[4q+2][c],W2[4q+3][c]}
// cAll[64]                  : b2 = {(b2_0,b2_1),(b2_2,b2_3)}
// W1/b1 are consumed RAW from the input pointers (their natural layout IS the pair packing).
__constant__ ulonglong2 cAll[65];
__device__   ulonglong2 g_stage[65];

__global__ void pack_weights(const float* __restrict__ W2, const float* __restrict__ b2f)
{
    const int t = threadIdx.x;   // 0..63
    ull* w2t = (ull*)g_stage;
    int e = t;
    #pragma unroll
    for (int k = 0; k < 2; ++k, e += 64) {
        const int ent = e >> 1, half = e & 1;   // ent = 4q+c
        const int q = ent >> 2, c = ent & 3;
        const int u0 = 4 * q + 2 * half;
        w2t[e] = pack2(W2[u0 * 4 + c], W2[(u0 + 1) * 4 + c]);
    }
    if (t == 0) {
        float* s = (float*)g_stage;
        s[256] = b2f[0]; s[257] = b2f[1]; s[258] = b2f[2]; s[259] = b2f[3];
    }
}

// Branchless 7-step counts over sorted a[0..63].
__device__ __forceinline__ int count_lt64(const float* __restrict__ a, float x) {
    int p = 0;
    p += (a[p + 31] < x) ? 32 : 0;
    p += (a[p + 15] < x) ? 16 : 0;
    p += (a[p + 7]  < x) ? 8  : 0;
    p += (a[p + 3]  < x) ? 4  : 0;
    p += (a[p + 1]  < x) ? 2  : 0;
    p += (a[p]      < x) ? 1  : 0;
    p += (a[p]      < x) ? 1  : 0;
    return p;
}
__device__ __forceinline__ int count_le64(const float* __restrict__ a, float x) {
    int p = 0;
    p += (a[p + 31] <= x) ? 32 : 0;
    p += (a[p + 15] <= x) ? 16 : 0;
    p += (a[p + 7]  <= x) ? 8  : 0;
    p += (a[p + 3]  <= x) ? 4  : 0;
    p += (a[p + 1]  <= x) ? 2  : 0;
    p += (a[p]      <= x) ? 1  : 0;
    p += (a[p]      <= x) ? 1  : 0;
    return p;
}

// Tiny MLP at TWO points of one ray, layer-1 folded: h = relu(P + z*Q).
// pq (shared, ulonglong2[32]): [j] = (P_pair_j, Q_pair_j), pair j = units {2j,2j+1}.
// Layer-2 weights + b2 from __constant__ (LDC warp-broadcast).
// Outputs (sigma, r, g, b) as float4 — directly storable payload.
__device__ __forceinline__ void field_eval2(
    float z0, float z1,
    const ulonglong2* __restrict__ pq,
    float4& o0, float4& o1)
{
    const ulonglong2* __restrict__ w2t = cAll;
    float b20, b21, b22, b23;
    unpack2(cAll[64].x, b20, b21);
    unpack2(cAll[64].y, b22, b23);
    const ull Z0 = pack2(z0, z0), Z1 = pack2(z1, z1);
    ull a00 = pack2(b20, 0.f), a01 = pack2(b21, 0.f);
    ull a02 = pack2(b22, 0.f), a03 = pack2(b23, 0.f);
    ull a10 = a00, a11 = a01, a12 = a02, a13 = a03;
    #pragma unroll
    for (int q = 0; q < 16; ++q) {
        const ulonglong2 p0 = pq[2 * q], p1 = pq[2 * q + 1];
        const ull h0a = relu2(fma2(Z0, p0.y, p0.x));
        const ull h0b = relu2(fma2(Z0, p1.y, p1.x));
        const ull h1a = relu2(fma2(Z1, p0.y, p0.x));
        const ull h1b = relu2(fma2(Z1, p1.y, p1.x));
        const ulonglong2 T0 = w2t[4 * q + 0], T1 = w2t[4 * q + 1];
        const ulonglong2 T2 = w2t[4 * q + 2], T3 = w2t[4 * q + 3];
        a00 = fma2(h0a, T0.x, a00); a00 = fma2(h0b, T0.y, a00);
        a01 = fma2(h0a, T1.x, a01); a01 = fma2(h0b, T1.y, a01);
        a02 = fma2(h0a, T2.x, a02); a02 = fma2(h0b, T2.y, a02);
        a03 = fma2(h0a, T3.x, a03); a03 = fma2(h0b, T3.y, a03);
        a10 = fma2(h1a, T0.x, a10); a10 = fma2(h1b, T0.y, a10);
        a11 = fma2(h1a, T1.x, a11); a11 = fma2(h1b, T1.y, a11);
        a12 = fma2(h1a, T2.x, a12); a12 = fma2(h1b, T2.y, a12);
        a13 = fma2(h1a, T3.x, a13); a13 = fma2(h1b, T3.y, a13);
    }
    float lo, hi;
    unpack2(a00, lo, hi); o0.x = lo + hi;
    unpack2(a01, lo, hi); o0.y = sigm(lo + hi);
    unpack2(a02, lo, hi); o0.z = sigm(lo + hi);
    unpack2(a03, lo, hi); o0.w = sigm(lo + hi);
    unpack2(a10, lo, hi); o1.x = lo + hi;
    unpack2(a11, lo, hi); o1.y = sigm(lo + hi);
    unpack2(a12, lo, hi); o1.z = sigm(lo + hi);
    unpack2(a13, lo, hi); o1.w = sigm(lo + hi);
}

__global__ void __launch_bounds__(RPB * 32, 10)
nerf_kernel(const float* __restrict__ ro,   const float* __restrict__ rdi,
            const float* __restrict__ tform, const float* __restrict__ noise,
            const float* __restrict__ usmp,
            const float* __restrict__ gW1, const float* __restrict__ gb1,
            float* __restrict__ orgb, float* __restrict__ odep, float* __restrict__ omsk)
{
    // Per-warp shared (3 KB): z (512B) + cdf/fine-z (512B) + payload (2 KB)
    __shared__ float  sZ [RPB][128];   // coarse z [0..63]; sorted all-z after scatter
    __shared__ float  sSg[RPB][128];   // cdf [0..62] + pad [63]; sorted fine z [64..127]
    __shared__ float4 sScat[RPB][128]; // pre-scatter: o-stash [0..63], PQ [96..127]
                                       // post-scatter: (sigma, r, g, b) per sorted sample

    const int tid = threadIdx.x;
    const int wrp = tid >> 5, lane = tid & 31;
    const int ray = blockIdx.x * RPB + wrp;
    float*  zw   = sZ[wrp];
    float*  sgw  = sSg[wrp];
    float*  sf   = sgw + 64;                 // sorted fine z
    float4* scat = sScat[wrp];

    const float ox = ro[ray * 3 + 0], oy = ro[ray * 3 + 1], oz = ro[ray * 3 + 2];
    float dx = rdi[ray * 3 + 0], dy = rdi[ray * 3 + 1], dz = rdi[ray * 3 + 2];
    {
        const float rinvn = rsqrtf(dx * dx + dy * dy + dz * dz);
        dx *= rinvn; dy *= rinvn; dz *= rinvn;
    }

    // ---- PQ precompute: W1/b1 read RAW from inputs (natural layout == pair packing) ----
    {
        const ull W1x = ((const ull*)gW1)[lane];
        const ull W1y = ((const ull*)(gW1 + 64))[lane];
        const ull W1z = ((const ull*)(gW1 + 128))[lane];
        const ull B1  = ((const ull*)gb1)[lane];
        const ull P = fma2(pack2(ox, ox), W1x, fma2(pack2(oy, oy), W1y, fma2(pack2(oz, oz), W1z, B1)));
        const ull Q = fma2(pack2(dx, dx), W1x, fma2(pack2(dy, dy), W1y, mul2(pack2(dz, dz), W1z)));
        ((ulonglong2*)&scat[96])[lane] = make_ulonglong2(P, Q);
    }
    const ulonglong2* __restrict__ pq = (const ulonglong2*)&scat[96];

    // ---- coarse stratified z (sorted by construction) + u prefetch ----
    const float2 nzp = ((const float2*)(noise + ray * 64))[lane];
    const float u0 = usmp[ray * 64 + lane];
    const float u1 = usmp[ray * 64 + lane + 32];
    const int i0 = 2 * lane, i1 = i0 + 1;
    const float z0 = NEARF + (FARF - NEARF) * (((float)i0 + nzp.x) * (1.f / 64.f));
    const float z1 = NEARF + (FARF - NEARF) * (((float)i1 + nzp.y) * (1.f / 64.f));
    zw[i0] = z0; zw[i1] = z1;
    // intra-phase neighbor traffic below goes through shfl; zw reads gated by later syncwarp

    // ---- coarse MLP; stash outputs to shared so they don't occupy regs ----
    float s1 = 0.f, s2 = 0.f;   // pooled pdf terms, built via shfl
    {
        float4 o0, o1;
        field_eval2(z0, z1, pq, o0, o1);
        scat[2 * lane]     = o0;
        scat[2 * lane + 1] = o1;

        // ---- coarse compositing weights (warp multiplicative scan; neighbors via shfl) ----
        const float d0 = z1 - z0;
        const float znx = __shfl_down_sync(FULL, z0, 1);   // zw[i1+1] == next lane's z0
        const float d1 = (lane == 31) ? 1e10f : (znx - z1);
        const float e0 = __expf(-fmaxf(o0.x, 0.f) * d0);
        const float e1 = __expf(-fmaxf(o1.x, 0.f) * d1);
        const float a0 = 1.f - e0, a1 = 1.f - e1;
        const float m0 = 1.f - a0 + 1e-10f, m1 = 1.f - a1 + 1e-10f;
        float v = m0 * m1;
        #pragma unroll
        for (int off = 1; off < 32; off <<= 1) {
            float t = __shfl_up_sync(FULL, v, off);
            if (lane >= off) v *= t;
        }
        float ex = __shfl_up_sync(FULL, v, 1);
        if (lane == 0) ex = 1.f;
        const float w0 = a0 * ex;          // weight at i0
        const float w1 = a1 * ex * m0;     // weight at i1
        const float w0n = __shfl_down_sync(FULL, w0, 1);
        const float w1n = __shfl_down_sync(FULL, w1, 1);
        if (lane < 31) {
            const float mA = fmaxf(w0, w1), mB = fmaxf(w1, w0n), mC = fmaxf(w0n, w1n);
            s1 = 0.5f * (mA + mB) + 0.01f;
            s2 = 0.5f * (mB + mC) + 0.01f;
        }
    }

    // ---- pdf -> cdf (63 entries in sgw[0..62]; sgw[63] = +pad) ----
    {
        const float pr = s1 + s2;
        float v = pr;
        #pragma unroll
        for (int off = 1; off < 32; off <<= 1) {
            float t = __shfl_up_sync(FULL, v, off);
            if (lane >= off) v += t;
        }
        const float tot = __shfl_sync(FULL, v, 30);
        const float rv = __fdividef(1.f, tot);
        const float ex = v - pr;
        if (lane == 0) { sgw[0] = 0.f; sgw[63] = 2.f; }
        if (lane < 31) {
            sgw[2 * lane + 1] = (ex + s1) * rv;
            sgw[2 * lane + 2] = v * rv;
        }
    }
    __syncwarp();   // orders zw writes + sgw writes before the searches below

    // ---- inverse-CDF fine samples (2 per lane, unsorted) ----
    float zs0 = 0.f, zs1 = 0.f;
    #pragma unroll
    for (int k = 0; k < 2; ++k) {
        const float u = (k == 0) ? u0 : u1;
        const int lo = count_le64(sgw, u);         // in [1,63] (cdf[0]=0 <= u, pad=2 > u)
        const int below = lo - 1;
        const int above = lo < 62 ? lo : 62;
        const float cbv = sgw[below], cav = sgw[above];
        float den = cav - cbv;
        if (den < 1e-5f) den = 1.f;
        const float t  = __fdividef(u - cbv, den);
        const float bb = 0.5f * (zw[below] + zw[below + 1]);
        const float ba = 0.5f * (zw[above] + zw[above + 1]);
        const float zz = fmaf(t, ba - bb, bb);
        if (k == 0) zs0 = zz; else zs1 = zz;
    }

    // ---- bitonic sort of the 64 fine samples (registers + shfl) ----
    float v0 = zs0, v1 = zs1;
    {
        const int e0l = lane, e1l = lane + 32;
        #pragma unroll
        for (int k = 2; k <= 64; k <<= 1) {
            #pragma unroll
            for (int j = k >> 1; j >= 1; j >>= 1) {
                if (j == 32) {
                    const float lo = fminf(v0, v1), hi = fmaxf(v0, v1);
                    v0 = lo; v1 = hi;
                } else {
                    const float t0 = __shfl_xor_sync(FULL, v0, j);
                    const bool keep0 = (((e0l & k) == 0) == ((e0l & j) == 0));
                    v0 = keep0 ? fminf(v0, t0) : fmaxf(v0, t0);
                    const float t1 = __shfl_xor_sync(FULL, v1, j);
                    const bool keep1 = (((e1l & k) == 0) == ((e1l & j) == 0));
                    v1 = keep1 ? fminf(v1, t1) : fmaxf(v1, t1);
                }
            }
        }
    }
    __syncwarp();                                  // cdf reads done before sf write
    sf[lane] = v0;
    sf[lane + 32] = v1;

    // ---- fine MLP at SORTED fine positions ----
    float4 f0, f1;
    field_eval2(v0, v1, pq, f0, f1);
    __syncwarp();                                  // sf fully written

    // ---- merge ranks: coarse sorted x fine sorted (branchless searches) ----
    const float zr0 = zw[i0], zr1 = zw[i1];
    const int r0 = i0 + count_lt64(sf, zr0);       // ties: coarse first
    const int r1 = i1 + count_lt64(sf, zr1);
    const int r2 = lane      + count_le64(zw, v0); // ties: fine after coarse
    const int r3 = lane + 32 + count_le64(zw, v1);
    const float4 o0 = scat[2 * lane];              // restore coarse outputs
    const float4 o1 = scat[2 * lane + 1];
    __syncwarp();                                  // all reads (incl. PQ, o-stash) done before scatter

    zw[r0] = zr0; scat[r0] = o0;
    zw[r1] = zr1; scat[r1] = o1;
    zw[r2] = v0;  scat[r2] = f0;
    zw[r3] = v1;  scat[r3] = f1;
    __syncwarp();

    // ---- final compositing over 128 sorted samples (4 per lane, vectorized loads) ----
    const int p = 4 * lane;
    const float4 zq = *(const float4*)(zw + p);
    const float  zn = (lane < 31) ? zw[p + 4] : 0.f;
    const float4 eA = scat[p], eB = scat[p + 1], eC = scat[p + 2], eD = scat[p + 3];

    const float dda = zq.y - zq.x, ddb = zq.z - zq.y, ddc = zq.w - zq.z;
    const float ddd = (lane == 31) ? 1e10f : (zn - zq.w);
    const float ea = __expf(-fmaxf(eA.x, 0.f) * dda);
    const float eb = __expf(-fmaxf(eB.x, 0.f) * ddb);
    const float ec = __expf(-fmaxf(eC.x, 0.f) * ddc);
    const float ed = __expf(-fmaxf(eD.x, 0.f) * ddd);
    const float aa = 1.f - ea, ab = 1.f - eb, ac = 1.f - ec, ad = 1.f - ed;
    const float ma = 1.f - aa + 1e-10f, mb = 1.f - ab + 1e-10f;
    const float mc = 1.f - ac + 1e-10f, md = 1.f - ad + 1e-10f;
    const float q0 = ma, q1 = ma * mb, q2 = q1 * mc, q3 = q2 * md;
    float v = q3;
    #pragma unroll
    for (int off = 1; off < 32; off <<= 1) {
        float t = __shfl_up_sync(FULL, v, off);
        if (lane >= off) v *= t;
    }
    float E = __shfl_up_sync(FULL, v, 1);
    if (lane == 0) E = 1.f;
    const float wA = aa * E, wB = ab * E * q0, wC = ac * E * q1, wD = ad * E * q2;

    float SW = wA + wB + wC + wD;
    float SZ = wA * zq.x + wB * zq.y + wC * zq.z + wD * zq.w;
    float SR = wA * eA.y + wB * eB.y + wC * eC.y + wD * eD.y;
    float SG = wA * eA.z + wB * eB.z + wC * eC.z + wD * eD.z;
    float SB = wA * eA.w + wB * eB.w + wC * eC.w + wD * eD.w;

    #pragma unroll
    for (int off = 16; off; off >>= 1) {
        SW += __shfl_xor_sync(FULL, SW, off);
        SZ += __shfl_xor_sync(FULL, SZ, off);
        SR += __shfl_xor_sync(FULL, SR, off);
        SG += __shfl_xor_sync(FULL, SG, off);
        SB += __shfl_xor_sync(FULL, SB, off);
    }

    if (lane == 0) {
        orgb[ray * 3 + 0] = SR;
        orgb[ray * 3 + 1] = SG;
        orgb[ray * 3 + 2] = SB;
        // reload + renormalize direction (cheaper than 3 regs live for the whole kernel)
        float ddx = rdi[ray * 3 + 0], ddy = rdi[ray * 3 + 1], ddz = rdi[ray * 3 + 2];
        const float rn = rsqrtf(ddx * ddx + ddy * ddy + ddz * ddz);
        const float* Tm = tform + (ray >> 12) * 16;
        const float vz = rn * (ddx * Tm[2] + ddy * Tm[6] + ddz * Tm[10]);
        odep[ray] = -vz * SZ;
        omsk[ray] = SW;
    }
}

extern "C" void kernel_launch(void* const* d_in, const int* in_sizes, int n_in,
                              void* d_out, int out_size)
{
    const float* ro    = (const float*)d_in[0];
    const float* rdi   = (const float*)d_in[1];
    const float* tform = (const float*)d_in[2];
    const float* noise = (const float*)d_in[3];
    const float* usmp  = (const float*)d_in[4];
    const float* W1    = (const float*)d_in[5];
    const float* b1    = (const float*)d_in[6];
    const float* W2    = (const float*)d_in[7];
    const float* b2    = (const float*)d_in[8];

    float* out = (float*)d_out;
    float* orgb = out;
    float* odep = out + RAYS_TOTAL * 3;
    float* omsk = odep + RAYS_TOTAL;

    pack_weights<<<1, 64>>>(W2, b2);
    void* stage_addr = nullptr;
    cudaGetSymbolAddress(&stage_addr, g_stage);
    cudaMemcpyToSymbolAsync(cAll, stage_addr, sizeof(g_stage), 0,
                            cudaMemcpyDeviceToDevice, 0);

    dim3 grid(RAYS_TOTAL / RPB);   // 4096 blocks, 1 ray per warp, 4 warps/block
    dim3 block(RPB * 32);
    nerf_kernel<<<grid, block>>>(ro, rdi, tform, noise, usmp, W1, b1,
                                 orgb, odep, omsk);
}